// round 1
// baseline (speedup 1.0000x reference)
#include <cuda_runtime.h>
#include <math.h>

// Problem constants (fixed by the dataset)
#define NB      16384      // batch
#define FEAT    2048       // feature size (GEMM K)
#define NCOL    2048       // FIELD*K = 32*64 (GEMM N)
#define TM      64         // CTA rows
#define TN      64         // CTA cols per n-tile (== one field: 64 k-values)
#define TK      16         // K tile
#define NT      (NCOL / TN)    // 32 n-tiles (= fields)
#define KT      (FEAT / TK)    // 128 k-tiles
#define NTHREADS 128
#define XSTR    66         // padded stride for transposed x tile (conflict-free)

typedef unsigned long long u64;

// ---- packed f32x2 helpers (Blackwell: FFMA2 only reachable via PTX) ----
__device__ __forceinline__ u64 pack2(float lo, float hi) {
    u64 r;
    asm("mov.b64 %0, {%1, %2};" : "=l"(r) : "f"(lo), "f"(hi));
    return r;
}
__device__ __forceinline__ float2 unpack2(u64 a) {
    float2 f;
    asm("mov.b64 {%0, %1}, %2;" : "=f"(f.x), "=f"(f.y) : "l"(a));
    return f;
}
__device__ __forceinline__ void ffma2(u64 &d, u64 a, u64 b) {
    asm("fma.rn.f32x2 %0, %1, %2, %0;" : "+l"(d) : "l"(a), "l"(b));
}
__device__ __forceinline__ void fadd2(u64 &d, u64 a) {
    asm("add.rn.f32x2 %0, %0, %1;" : "+l"(d) : "l"(a));
}

// Fused FFM kernel:
//   y[b, n] = x[b, :] . V[:, n]        (V = v reshaped [FEAT, NCOL], row-major)
//   s[b, k]  = sum over fields of y    (k = n % 64; each 64-wide n-tile == 1 field)
//   sq[b]    = sum over n of y^2
//   out[b]   = sigmoid(x.w + bias + 0.5*(sum_k s^2 - sq))
//
// Thread layout: 128 threads = 8 ty * 16 tx.
//   thread rows: ty*8 .. ty*8+7 (4 row-pairs, packed f32x2)
//   thread cols: tx*4 .. tx*4+3 (== k-indices tx*4+j, identical for every field)
// => per-thread s2[j][p] accumulates the TRUE s[row][k] across fields in regs,
//    no cross-thread mixing until the final shuffle reduction.
__global__ void __launch_bounds__(NTHREADS, 2)
ffm_kernel(const float* __restrict__ x,
           const float* __restrict__ w,
           const float* __restrict__ bias,
           const float* __restrict__ v,
           float* __restrict__ out)
{
    __shared__ float xs[2][TK][XSTR];   // x tile, transposed [k][row]
    __shared__ float vs[2][TK][TN];     // V tile [k][n]

    const int tid  = threadIdx.x;
    const int tx   = tid & 15;
    const int ty   = tid >> 4;
    const int rblk = blockIdx.x * TM;
    const int r0   = ty * 8;

    // x-tile global->smem mapping: TM*TK = 1024 floats = 2 float4 / thread
    const int xrow0 = tid >> 2;          // 0..31 (second chunk: +32)
    const int xkq   = (tid & 3) * 4;
    // v-tile mapping: TK*TN = 1024 floats = 2 float4 / thread
    const int vrow0 = tid >> 4;          // 0..7 (second chunk: +8)
    const int vcol  = (tid & 15) * 4;

    const float* xg = x + rblk * FEAT;

    u64 s2[4][4];   // [col j][row-pair p] : s[row][k] accumulated over fields
    u64 sq2[4];     // [row-pair p]        : sum of y^2 over this thread's cols
    #pragma unroll
    for (int j = 0; j < 4; ++j)
        #pragma unroll
        for (int p = 0; p < 4; ++p) s2[j][p] = 0ull;
    #pragma unroll
    for (int p = 0; p < 4; ++p) sq2[p] = 0ull;

    for (int nt = 0; nt < NT; ++nt) {
        u64 acc[4][4];
        #pragma unroll
        for (int j = 0; j < 4; ++j)
            #pragma unroll
            for (int p = 0; p < 4; ++p) acc[j][p] = 0ull;

        // ---- preload k-tile 0 ----
        float4 xv0 = *(const float4*)(xg + xrow0 * FEAT + xkq);
        float4 xv1 = *(const float4*)(xg + (xrow0 + 32) * FEAT + xkq);
        float4 vv0 = *(const float4*)(v + (size_t)vrow0 * NCOL + nt * TN + vcol);
        float4 vv1 = *(const float4*)(v + (size_t)(vrow0 + 8) * NCOL + nt * TN + vcol);

        xs[0][xkq + 0][xrow0] = xv0.x;
        xs[0][xkq + 1][xrow0] = xv0.y;
        xs[0][xkq + 2][xrow0] = xv0.z;
        xs[0][xkq + 3][xrow0] = xv0.w;
        xs[0][xkq + 0][xrow0 + 32] = xv1.x;
        xs[0][xkq + 1][xrow0 + 32] = xv1.y;
        xs[0][xkq + 2][xrow0 + 32] = xv1.z;
        xs[0][xkq + 3][xrow0 + 32] = xv1.w;
        *(float4*)&vs[0][vrow0][vcol]     = vv0;
        *(float4*)&vs[0][vrow0 + 8][vcol] = vv1;
        __syncthreads();

        // ---- main K loop, double buffered ----
        for (int kt = 0; kt < KT; ++kt) {
            const int  cur  = kt & 1;
            const bool more = (kt + 1) < KT;
            if (more) {
                const int kb = (kt + 1) * TK;
                xv0 = *(const float4*)(xg + xrow0 * FEAT + kb + xkq);
                xv1 = *(const float4*)(xg + (xrow0 + 32) * FEAT + kb + xkq);
                vv0 = *(const float4*)(v + (size_t)(kb + vrow0) * NCOL + nt * TN + vcol);
                vv1 = *(const float4*)(v + (size_t)(kb + vrow0 + 8) * NCOL + nt * TN + vcol);
            }

            const float (*xsb)[XSTR] = xs[cur];
            const float (*vsb)[TN]   = vs[cur];
            #pragma unroll
            for (int k = 0; k < TK; ++k) {
                u64 a2[4];
                #pragma unroll
                for (int p = 0; p < 4; ++p)
                    a2[p] = *(const u64*)&xsb[k][r0 + 2 * p];   // rows (r0+2p, r0+2p+1)
                float4 bb = *(const float4*)&vsb[k][tx * 4];
                u64 b2[4];
                b2[0] = pack2(bb.x, bb.x);
                b2[1] = pack2(bb.y, bb.y);
                b2[2] = pack2(bb.z, bb.z);
                b2[3] = pack2(bb.w, bb.w);
                #pragma unroll
                for (int j = 0; j < 4; ++j)
                    #pragma unroll
                    for (int p = 0; p < 4; ++p)
                        ffma2(acc[j][p], a2[p], b2[j]);
            }

            if (more) {
                const int nb = cur ^ 1;
                xs[nb][xkq + 0][xrow0] = xv0.x;
                xs[nb][xkq + 1][xrow0] = xv0.y;
                xs[nb][xkq + 2][xrow0] = xv0.z;
                xs[nb][xkq + 3][xrow0] = xv0.w;
                xs[nb][xkq + 0][xrow0 + 32] = xv1.x;
                xs[nb][xkq + 1][xrow0 + 32] = xv1.y;
                xs[nb][xkq + 2][xrow0 + 32] = xv1.z;
                xs[nb][xkq + 3][xrow0 + 32] = xv1.w;
                *(float4*)&vs[nb][vrow0][vcol]     = vv0;
                *(float4*)&vs[nb][vrow0 + 8][vcol] = vv1;
            }
            __syncthreads();
        }

        // ---- fold this field's y into s and sq ----
        #pragma unroll
        for (int j = 0; j < 4; ++j)
            #pragma unroll
            for (int p = 0; p < 4; ++p) {
                fadd2(s2[j][p], acc[j][p]);
                ffma2(sq2[p], acc[j][p], acc[j][p]);
            }
    }

    // ---- epilogue: interaction value per row ----
    float val[8];
    #pragma unroll
    for (int p = 0; p < 4; ++p) {
        u64 it = 0ull;
        #pragma unroll
        for (int j = 0; j < 4; ++j) ffma2(it, s2[j][p], s2[j][p]);
        float2 itf = unpack2(it);
        float2 sqf = unpack2(sq2[p]);
        val[2 * p]     = 0.5f * (itf.x - sqf.x);
        val[2 * p + 1] = 0.5f * (itf.y - sqf.y);
    }

    // ---- linear part: rows r0..r0+7, k-chunk [tx*128, tx*128+128) ----
    {
        const int kb = tx * 128;
        float lacc[8];
        #pragma unroll
        for (int r = 0; r < 8; ++r) lacc[r] = 0.0f;
        for (int kk = 0; kk < 128; kk += 4) {
            float4 wv = *(const float4*)(w + kb + kk);
            #pragma unroll
            for (int r = 0; r < 8; ++r) {
                float4 xv = *(const float4*)(xg + (r0 + r) * FEAT + kb + kk);
                lacc[r] += xv.x * wv.x + xv.y * wv.y + xv.z * wv.z + xv.w * wv.w;
            }
        }
        #pragma unroll
        for (int r = 0; r < 8; ++r) val[r] += lacc[r];
    }

    // ---- reduce over the 16 tx lanes (same ty-half of the warp) ----
    #pragma unroll
    for (int m = 1; m < 16; m <<= 1)
        #pragma unroll
        for (int r = 0; r < 8; ++r)
            val[r] += __shfl_xor_sync(0xffffffffu, val[r], m);

    if (tx == 0) {
        const float bsc = bias[0];
        #pragma unroll
        for (int r = 0; r < 8; ++r) {
            float z = val[r] + bsc;
            out[rblk + r0 + r] = 1.0f / (1.0f + expf(-z));
        }
    }
}

extern "C" void kernel_launch(void* const* d_in, const int* in_sizes, int n_in,
                              void* d_out, int out_size) {
    const float* x = (const float*)d_in[0];
    const float* w = (const float*)d_in[1];
    const float* b = (const float*)d_in[2];
    const float* v = (const float*)d_in[3];
    float* out = (float*)d_out;

    ffm_kernel<<<NB / TM, NTHREADS>>>(x, w, b, v, out);
}

// round 3
// speedup vs baseline: 1.8672x; 1.8672x over previous
#include <cuda_runtime.h>
#include <cuda_bf16.h>
#include <math.h>
#include <stdint.h>

// ---------------- problem constants ----------------
#define NB      16384
#define FEAT    2048
#define NCOL    2048          // FIELD(32) * K(64)
#define MTILE   128           // rows per CTA
#define NPASS   128           // n-cols per pass (2 fields)
#define NPASSES (NCOL/NPASS)  // 16
#define KT      32            // k per smem stage
#define NST     (FEAT/KT)     // 64 stages
#define THREADS 256
#define ROWB    80            // padded smem row stride: 64B data + 16B pad (LDSM conflict-free)
#define MATB    (MTILE*ROWB)  // 10240 bytes per matrix tile
#define STAGE   (4*MATB)      // xh, xl, vh, vl
#define SMEM_TOTAL (2*STAGE)  // 81920, double buffered

// ---------------- device scratch (alloc-free rule: __device__ globals) ----------------
__device__ __nv_bfloat16 g_xh[(size_t)NB*FEAT];
__device__ __nv_bfloat16 g_xl[(size_t)NB*FEAT];
__device__ __nv_bfloat16 g_vh[(size_t)NCOL*FEAT];   // [n][k] (transposed)
__device__ __nv_bfloat16 g_vl[(size_t)NCOL*FEAT];
__device__ float         g_lin[NB];

// ---------------- PTX helpers (all sm_80-era: safe for compute_103) ----------------
__device__ __forceinline__ uint32_t smem_u32(const void* p) {
    uint32_t a;
    asm("{ .reg .u64 t; cvta.to.shared.u64 t, %1; cvt.u32.u64 %0, t; }" : "=r"(a) : "l"(p));
    return a;
}
__device__ __forceinline__ void cp16(uint32_t saddr, const void* gptr) {
    asm volatile("cp.async.cg.shared.global [%0], [%1], 16;" :: "r"(saddr), "l"(gptr) : "memory");
}
__device__ __forceinline__ void cpcommit() {
    asm volatile("cp.async.commit_group;" ::: "memory");
}
template<int N> __device__ __forceinline__ void cpwait() {
    asm volatile("cp.async.wait_group %0;" :: "n"(N) : "memory");
}
__device__ __forceinline__ void ldsm4(uint32_t* r, uint32_t addr) {
    asm volatile("ldmatrix.sync.aligned.m8n8.x4.shared.b16 {%0,%1,%2,%3}, [%4];"
                 : "=r"(r[0]), "=r"(r[1]), "=r"(r[2]), "=r"(r[3]) : "r"(addr));
}
__device__ __forceinline__ void mma16816(float* d, const uint32_t* a,
                                         uint32_t b0, uint32_t b1) {
    asm volatile(
        "mma.sync.aligned.m16n8k16.row.col.f32.bf16.bf16.f32 "
        "{%0,%1,%2,%3}, {%4,%5,%6,%7}, {%8,%9}, {%0,%1,%2,%3};"
        : "+f"(d[0]), "+f"(d[1]), "+f"(d[2]), "+f"(d[3])
        : "r"(a[0]), "r"(a[1]), "r"(a[2]), "r"(a[3]), "r"(b0), "r"(b1));
}

// ---------------- prep kernels ----------------
__global__ void __launch_bounds__(256) prep_x(const float* __restrict__ x,
                                              const float* __restrict__ w) {
    const int row = blockIdx.x;
    const int t = threadIdx.x;
    const size_t base = (size_t)row * FEAT;
    float dot = 0.f;
#pragma unroll
    for (int i = 0; i < FEAT / 256; ++i) {
        int k = t + i * 256;
        float xv = x[base + k];
        __nv_bfloat16 h = __float2bfloat16(xv);
        float hf = __bfloat162float(h);
        g_xh[base + k] = h;
        g_xl[base + k] = __float2bfloat16(xv - hf);
        dot = fmaf(xv, w[k], dot);
    }
#pragma unroll
    for (int m = 16; m > 0; m >>= 1) dot += __shfl_xor_sync(0xffffffffu, dot, m);
    __shared__ float part[8];
    if ((t & 31) == 0) part[t >> 5] = dot;
    __syncthreads();
    if (t == 0) {
        float s = 0.f;
#pragma unroll
        for (int i = 0; i < 8; ++i) s += part[i];
        g_lin[row] = s;
    }
}

// transpose v [FEAT][NCOL] -> g_vh/g_vl [NCOL][FEAT], split bf16 hi/lo
__global__ void __launch_bounds__(256) prep_v(const float* __restrict__ v) {
    __shared__ float tile[32][33];
    const int k0 = blockIdx.x * 32;
    const int n0 = blockIdx.y * 32;
    const int tx = threadIdx.x;
    const int ty = threadIdx.y;
#pragma unroll
    for (int i = 0; i < 32; i += 8)
        tile[ty + i][tx] = v[(size_t)(k0 + ty + i) * NCOL + n0 + tx];
    __syncthreads();
#pragma unroll
    for (int i = 0; i < 32; i += 8) {
        float val = tile[tx][ty + i];
        size_t o = (size_t)(n0 + ty + i) * FEAT + k0 + tx;
        __nv_bfloat16 h = __float2bfloat16(val);
        float hf = __bfloat162float(h);
        g_vh[o] = h;
        g_vl[o] = __float2bfloat16(val - hf);
    }
}

// ---------------- main fused split-bf16 GEMM + FFM kernel ----------------
// Warp layout: 8 warps = 4 warp_m x 2 warp_n. Warp tile M=32, N=64.
// warp_n selects the field within the 128-wide pass (2 fields/pass).
// Thread fragment columns map to IDENTICAL k-slots every pass, so s[] lives in regs.
__global__ void __launch_bounds__(THREADS, 1)
ffm_main(const float* __restrict__ bias, float* __restrict__ out) {
    extern __shared__ char smem[];
    const uint32_t sb = smem_u32(smem);
    const int tid  = threadIdx.x;
    const int lane = tid & 31;
    const int wid  = tid >> 5;
    const int wm   = wid >> 1;         // 0..3
    const int wn   = wid & 1;          // 0..1 (field parity)
    const int rblk = blockIdx.x * MTILE;

    // LDSM lane address components
    const int lrow = lane & 15;
    const int lkb  = (lane >> 4) * 16;

    // cp.async per-thread mapping: 8 chunks of 16B; id -> (mat, row, quarter)
    int cp_mat[8], cp_row[8], cp_q[8];
#pragma unroll
    for (int i = 0; i < 8; ++i) {
        const int id = tid + i * 256;
        cp_mat[i] = id >> 9;
        cp_row[i] = (id >> 2) & 127;
        cp_q[i]   = id & 3;
    }

    float s[2][8][4];     // field-sum accumulators (per-thread fixed k-slots)
    float sqr[2][2];      // sum of y^2 per owned row (i, h)
#pragma unroll
    for (int i = 0; i < 2; ++i)
#pragma unroll
        for (int j = 0; j < 8; ++j)
#pragma unroll
            for (int c = 0; c < 4; ++c) s[i][j][c] = 0.f;
    sqr[0][0] = sqr[0][1] = sqr[1][0] = sqr[1][1] = 0.f;

    for (int p = 0; p < NPASSES; ++p) {
        float acc[2][8][4];
#pragma unroll
        for (int i = 0; i < 2; ++i)
#pragma unroll
            for (int j = 0; j < 8; ++j)
#pragma unroll
                for (int c = 0; c < 4; ++c) acc[i][j][c] = 0.f;

        // ---- stage loader ----
        auto load_stage = [&](int st) {
            const uint32_t dst = sb + (st & 1) * STAGE;
            const int k0 = st * KT;
#pragma unroll
            for (int i = 0; i < 8; ++i) {
                const int mat = cp_mat[i], row = cp_row[i], q = cp_q[i];
                const uint32_t so = dst + mat * MATB + row * ROWB + q * 16;
                const __nv_bfloat16* g =
                    (mat == 0) ? g_xh : (mat == 1) ? g_xl : (mat == 2) ? g_vh : g_vl;
                const size_t go = (mat < 2)
                    ? ((size_t)(rblk + row) * FEAT + k0 + q * 8)
                    : ((size_t)(p * NPASS + row) * FEAT + k0 + q * 8);
                cp16(so, g + go);
            }
            cpcommit();
        };

        load_stage(0);
        for (int st = 0; st < NST; ++st) {
            if (st + 1 < NST) { load_stage(st + 1); cpwait<1>(); }
            else              { cpwait<0>(); }
            __syncthreads();

            const uint32_t abase = sb + (st & 1) * STAGE;
#pragma unroll
            for (int kk = 0; kk < 2; ++kk) {     // two k16 steps per stage
                uint32_t ah[2][4], al[2][4];
#pragma unroll
                for (int i = 0; i < 2; ++i) {
                    const uint32_t ao = abase + (uint32_t)((wm * 32 + i * 16 + lrow) * ROWB
                                                           + kk * 32 + lkb);
                    ldsm4(ah[i], ao);
                    ldsm4(al[i], ao + MATB);
                }
#pragma unroll
                for (int g = 0; g < 4; ++g) {
                    const uint32_t bo = abase + 2 * MATB
                        + (uint32_t)((wn * 64 + g * 16 + lrow) * ROWB + kk * 32 + lkb);
                    uint32_t bh[4], bl[4];
                    ldsm4(bh, bo);
                    ldsm4(bl, bo + MATB);
#pragma unroll
                    for (int i = 0; i < 2; ++i) {
                        float* d0 = acc[i][2 * g];
                        float* d1 = acc[i][2 * g + 1];
                        mma16816(d0, ah[i], bh[0], bh[2]);
                        mma16816(d0, ah[i], bl[0], bl[2]);
                        mma16816(d0, al[i], bh[0], bh[2]);
                        mma16816(d1, ah[i], bh[1], bh[3]);
                        mma16816(d1, ah[i], bl[1], bl[3]);
                        mma16816(d1, al[i], bh[1], bh[3]);
                    }
                }
            }
            __syncthreads();
        }

        // ---- fold this pass's y into s and sq ----
#pragma unroll
        for (int i = 0; i < 2; ++i)
#pragma unroll
            for (int j = 0; j < 8; ++j)
#pragma unroll
                for (int c = 0; c < 4; ++c) {
                    const float y = acc[i][j][c];
                    s[i][j][c] += y;
                    sqr[i][c >> 1] = fmaf(y, y, sqr[i][c >> 1]);
                }
    }

    // ---- final epilogue: merge s across warp_n pairs, square-sum, sigmoid ----
    __syncthreads();
    float* sbuf = (float*)smem;                 // 4*32*64 floats = 32KB
    float* zbuf = (float*)(smem + 32768);       // 128 floats
    if (tid < MTILE) zbuf[tid] = 0.f;
    if (wn == 1) {
        const int base = (wm * 32 + lane) * 64;
#pragma unroll
        for (int i = 0; i < 2; ++i)
#pragma unroll
            for (int j = 0; j < 8; ++j)
#pragma unroll
                for (int c = 0; c < 4; ++c)
                    sbuf[base + i * 32 + j * 4 + c] = s[i][j][c];
    }
    __syncthreads();

    float contrib[2][2];    // per (i, h) row: inter - sq contribution
    contrib[0][0] = contrib[0][1] = contrib[1][0] = contrib[1][1] = 0.f;
    if (wn == 0) {
        const int base = (wm * 32 + lane) * 64;
#pragma unroll
        for (int i = 0; i < 2; ++i)
#pragma unroll
            for (int j = 0; j < 8; ++j)
#pragma unroll
                for (int c = 0; c < 4; ++c) {
                    const float st = s[i][j][c] + sbuf[base + i * 32 + j * 4 + c];
                    contrib[i][c >> 1] = fmaf(st, st, contrib[i][c >> 1]);
                }
    }
#pragma unroll
    for (int i = 0; i < 2; ++i)
#pragma unroll
        for (int h = 0; h < 2; ++h)
            contrib[i][h] -= sqr[i][h];

    // reduce over the 4 lanes of each quad (they own disjoint k-slots, same rows)
#pragma unroll
    for (int m = 1; m < 4; m <<= 1)
#pragma unroll
        for (int i = 0; i < 2; ++i)
#pragma unroll
            for (int h = 0; h < 2; ++h)
                contrib[i][h] += __shfl_xor_sync(0xffffffffu, contrib[i][h], m);

    if ((lane & 3) == 0) {
#pragma unroll
        for (int i = 0; i < 2; ++i)
#pragma unroll
            for (int h = 0; h < 2; ++h) {
                const int row = wm * 32 + i * 16 + (lane >> 2) + h * 8;
                atomicAdd(&zbuf[row], contrib[i][h]);
            }
    }
    __syncthreads();

    if (tid < MTILE) {
        const int g = rblk + tid;
        const float z = 0.5f * zbuf[tid] + g_lin[g] + bias[0];
        out[g] = 1.f / (1.f + expf(-z));
    }
}

// ---------------- launch ----------------
extern "C" void kernel_launch(void* const* d_in, const int* in_sizes, int n_in,
                              void* d_out, int out_size) {
    const float* x = (const float*)d_in[0];
    const float* w = (const float*)d_in[1];
    const float* b = (const float*)d_in[2];
    const float* v = (const float*)d_in[3];
    float* out = (float*)d_out;

    cudaFuncSetAttribute(ffm_main, cudaFuncAttributeMaxDynamicSharedMemorySize, SMEM_TOTAL);

    prep_x<<<NB, 256>>>(x, w);
    prep_v<<<dim3(FEAT / 32, NCOL / 32), dim3(32, 8)>>>(v);
    ffm_main<<<NB / MTILE, THREADS, SMEM_TOTAL>>>(b, out);
}